// round 15
// baseline (speedup 1.0000x reference)
#include <cuda_runtime.h>
#include <cuda_fp16.h>
#include <cstdint>
#include <math.h>

#define D 256
#define F 1024
#define CLS 40
#define NMAX 50000
#define EMAX 300000
#define ROWW 20  // padded words per 32-half tile row (bank-conflict-free bijection)

// ---------------- scratch (static device memory; no allocations) ----------------
__device__ __half g_Fh[NMAX * F];     // fp16 copy of feat
__device__ __half g_Xh[NMAX * D];
__device__ __half g_Yh[NMAX * D];
__device__ __half g_Mh[NMAX * D];
__device__ __half g_Wth[256 * 1024];  // transposed fp16 weights [n][k], reused per layer
__device__ float g_degout[NMAX];
__device__ float g_degin[NMAX];
__device__ float g_ns[NMAX];
__device__ float g_nd[NMAX];
__device__ float g_sum[D];
__device__ float g_sumsq[D];
__device__ float g_scale[D];
__device__ float g_shift[D];
// CSR by dst
__device__ int g_cnt[NMAX];
__device__ int g_rowptr[NMAX + 1];
__device__ int g_cursor[NMAX];
__device__ int g_esrc[EMAX];
__device__ int g_bsum[256];
__device__ int g_boff[256];

__device__ __forceinline__ uint32_t tf32r(float x) {
    uint32_t r;
    asm("cvt.rna.tf32.f32 %0, %1;" : "=r"(r) : "f"(x));
    return r;
}
__device__ __forceinline__ uint32_t h2pack(float lo, float hi) {
    __half2 h = __floats2half2_rn(lo, hi);
    return *(uint32_t*)&h;
}

// ---------------- feat fp32 -> fp16 ----------------
__global__ void f2h_k(const float4* __restrict__ in, uint2* __restrict__ out, int n4) {
    int i = blockIdx.x * blockDim.x + threadIdx.x;
    if (i >= n4) return;
    float4 v = in[i];
    uint2 o;
    o.x = h2pack(v.x, v.y);
    o.y = h2pack(v.z, v.w);
    out[i] = o;
}

// ---------------- weight transpose+convert: W[K][256] fp32 -> Wt[256][K] fp16 ----
__global__ void wt_k(const float* __restrict__ W, __half* __restrict__ Wt, int K) {
    __shared__ float t[32][33];
    int k0 = blockIdx.x * 32, n0 = blockIdx.y * 32;
    int x = threadIdx.x, y = threadIdx.y;  // 32 x 8
    for (int j = y; j < 32; j += 8) t[j][x] = W[(size_t)(k0 + j) * 256 + n0 + x];
    __syncthreads();
    for (int j = y; j < 32; j += 8)
        Wt[(size_t)(n0 + j) * K + k0 + x] = __float2half(t[x][j]);
}

// ================= shared GEMM building blocks =================
#define TILE_WORDS (128 * ROWW)  // 2560 words per A or B buffer

// ldmatrix-based fragment load + MMA for one 32-deep chunk buffer.
// sA/sB are shared-space byte addresses of the A and B tile buffers.
__device__ __forceinline__ void gemm_compute_chunk(
    uint32_t sA, uint32_t sB, int wm, int wn, int lane, float (&acc)[4][4][4]) {
    const int lr = lane & 15;
    const int lc = lane >> 4;
#pragma unroll
    for (int kk = 0; kk < 2; kk++) {
        uint32_t afr[4][4];
        uint32_t bfr[4][2];
        const uint32_t coff = (kk * 16 + lc * 8) * 2;
#pragma unroll
        for (int im = 0; im < 4; im++) {
            int m = wm * 64 + im * 16 + lr;
            uint32_t addr = sA + m * (ROWW * 4) + coff;
            asm volatile(
                "ldmatrix.sync.aligned.m8n8.x4.shared.b16 {%0,%1,%2,%3}, [%4];"
                : "=r"(afr[im][0]), "=r"(afr[im][1]),
                  "=r"(afr[im][2]), "=r"(afr[im][3])
                : "r"(addr));
        }
#pragma unroll
        for (int ib = 0; ib < 2; ib++) {
            int n = wn * 32 + ib * 16 + lr;
            uint32_t addr = sB + n * (ROWW * 4) + coff;
            uint32_t r0, r1, r2, r3;
            asm volatile(
                "ldmatrix.sync.aligned.m8n8.x4.shared.b16 {%0,%1,%2,%3}, [%4];"
                : "=r"(r0), "=r"(r1), "=r"(r2), "=r"(r3)
                : "r"(addr));
            bfr[2 * ib][0] = r0; bfr[2 * ib + 1][0] = r1;
            bfr[2 * ib][1] = r2; bfr[2 * ib + 1][1] = r3;
        }
#pragma unroll
        for (int im = 0; im < 4; im++)
#pragma unroll
            for (int in = 0; in < 4; in++)
                asm volatile(
                    "mma.sync.aligned.m16n8k16.row.col.f32.f16.f16.f32 "
                    "{%0,%1,%2,%3}, {%4,%5,%6,%7}, {%8,%9}, {%0,%1,%2,%3};"
                    : "+f"(acc[im][in][0]), "+f"(acc[im][in][1]),
                      "+f"(acc[im][in][2]), "+f"(acc[im][in][3])
                    : "r"(afr[im][0]), "r"(afr[im][1]), "r"(afr[im][2]), "r"(afr[im][3]),
                      "r"(bfr[in][0]), "r"(bfr[in][1]));
    }
}

// Shared epilogue: bias, store (fp16 or fp32), optional fused column stats.
template <int C_HALF>
__device__ __forceinline__ void gemm_epilogue(
    void* Cv, const float* bias, int M, int row0, int col0,
    int wm, int wn, int lane, float (&acc)[4][4][4], int doStats) {
    float s_[4][2] = {{0.f}}, q_[4][2] = {{0.f}};
#pragma unroll
    for (int im = 0; im < 4; im++) {
        int rl = row0 + wm * 64 + im * 16 + (lane >> 2);
        int rh = rl + 8;
        bool vl = rl < M, vh = rh < M;
#pragma unroll
        for (int in = 0; in < 4; in++) {
            int cc = col0 + wn * 32 + in * 8 + (lane & 3) * 2;
            float b0 = bias[cc], b1 = bias[cc + 1];
            float v0 = acc[im][in][0] + b0, v1 = acc[im][in][1] + b1;
            float v2 = acc[im][in][2] + b0, v3 = acc[im][in][3] + b1;
            if (vl) {
                if (C_HALF)
                    *(__half2*)((__half*)Cv + (size_t)rl * 256 + cc) = __floats2half2_rn(v0, v1);
                else
                    *(float2*)((float*)Cv + (size_t)rl * 256 + cc) = make_float2(v0, v1);
                s_[in][0] += v0; q_[in][0] += v0 * v0;
                s_[in][1] += v1; q_[in][1] += v1 * v1;
            }
            if (vh) {
                if (C_HALF)
                    *(__half2*)((__half*)Cv + (size_t)rh * 256 + cc) = __floats2half2_rn(v2, v3);
                else
                    *(float2*)((float*)Cv + (size_t)rh * 256 + cc) = make_float2(v2, v3);
                s_[in][0] += v2; q_[in][0] += v2 * v2;
                s_[in][1] += v3; q_[in][1] += v3 * v3;
            }
        }
    }
    if (doStats) {
#pragma unroll
        for (int in = 0; in < 4; in++)
#pragma unroll
            for (int t = 0; t < 2; t++) {
#pragma unroll
                for (int m = 4; m < 32; m <<= 1) {
                    s_[in][t] += __shfl_xor_sync(0xFFFFFFFF, s_[in][t], m);
                    q_[in][t] += __shfl_xor_sync(0xFFFFFFFF, q_[in][t], m);
                }
            }
        if ((lane >> 2) == 0) {
#pragma unroll
            for (int in = 0; in < 4; in++)
#pragma unroll
                for (int t = 0; t < 2; t++) {
                    int cc = col0 + wn * 32 + in * 8 + (lane & 3) * 2 + t;
                    atomicAdd(&g_sum[cc], s_[in][t]);
                    atomicAdd(&g_sumsq[cc], q_[in][t]);
                }
        }
    }
}

// ---------------- FC GEMM: cp.async 3-stage + ldmatrix (long K) ----------------
#define NSTAGE 3
#define GEMM_SMEM_CA (NSTAGE * 2 * TILE_WORDS * 4)  // 61440 B

__global__ __launch_bounds__(256, 2) void h_gemm_ca(
    const __half* __restrict__ Ah, const __half* __restrict__ Wt,
    const float* __restrict__ bias, void* __restrict__ Cv,
    int M, int K, int doStats) {
    extern __shared__ uint32_t dsm[];
    const uint32_t sbase = (uint32_t)__cvta_generic_to_shared(dsm);

    const int tid = threadIdx.x;
    const int lane = tid & 31;
    const int wid = tid >> 5;
    const int wm = wid >> 2, wn = wid & 3;
    const int row0 = blockIdx.y * 128;
    const int col0 = blockIdx.x * 128;

    float acc[4][4][4];
#pragma unroll
    for (int i = 0; i < 4; i++)
#pragma unroll
        for (int j = 0; j < 4; j++)
#pragma unroll
            for (int t = 0; t < 4; t++) acc[i][j][t] = 0.0f;

    const int nch = K >> 5;

    auto issue = [&](int buf, int k0) {
        uint32_t sA = sbase + buf * 2 * TILE_WORDS * 4;
        uint32_t sB = sA + TILE_WORDS * 4;
#pragma unroll
        for (int j = 0; j < 2; j++) {
            int id = tid + 256 * j;
            int r = id >> 2, sq = id & 3;
            uint32_t soff = (r * ROWW + 4 * sq) * 4;
            int gr = row0 + r;
            int grc = gr < M ? gr : 0;
            const __half* ga = Ah + (size_t)grc * K + k0 + 8 * sq;
            int sz = (gr < M) ? 16 : 0;
            asm volatile("cp.async.cg.shared.global [%0], [%1], 16, %2;"
                         :: "r"(sA + soff), "l"(ga), "r"(sz) : "memory");
            const __half* gb = Wt + (size_t)(col0 + r) * K + k0 + 8 * sq;
            asm volatile("cp.async.cg.shared.global [%0], [%1], 16;"
                         :: "r"(sB + soff), "l"(gb) : "memory");
        }
        asm volatile("cp.async.commit_group;" ::: "memory");
    };

    issue(0, 0);
    issue(1, 32);

    for (int ch = 0; ch < nch; ch++) {
        const int s = ch % 3;
        if (ch == nch - 1)
            asm volatile("cp.async.wait_group 0;" ::: "memory");
        else
            asm volatile("cp.async.wait_group 1;" ::: "memory");
        __syncthreads();
        if (ch + 2 < nch) issue((ch + 2) % 3, (ch + 2) * 32);
        uint32_t sA = sbase + s * 2 * TILE_WORDS * 4;
        gemm_compute_chunk(sA, sA + TILE_WORDS * 4, wm, wn, lane, acc);
    }

    gemm_epilogue<1>(Cv, bias, M, row0, col0, wm, wn, lane, acc, doStats);
}

// ---------------- D-GEMM: register double-buffer staging + ldmatrix ----------------
#define GEMM_SMEM_RB (4 * TILE_WORDS * 4)  // 40960 B

template <int C_HALF>
__global__ __launch_bounds__(256, 2) void h_gemm_rb(
    const __half* __restrict__ Ah, const __half* __restrict__ Wt,
    const float* __restrict__ bias, void* __restrict__ Cv,
    int M, int K, int doStats) {
    extern __shared__ uint32_t dsm[];
    const uint32_t sbase = (uint32_t)__cvta_generic_to_shared(dsm);

    const int tid = threadIdx.x;
    const int lane = tid & 31;
    const int wid = tid >> 5;
    const int wm = wid >> 2, wn = wid & 3;
    const int row0 = blockIdx.y * 128;
    const int col0 = blockIdx.x * 128;

    const int srow = tid >> 2;  // 0..63
    const int sq = tid & 3;

    float acc[4][4][4];
#pragma unroll
    for (int i = 0; i < 4; i++)
#pragma unroll
        for (int j = 0; j < 4; j++)
#pragma unroll
            for (int t = 0; t < 4; t++) acc[i][j][t] = 0.0f;

    const int nch = K >> 5;
    uint4 ar[2], br[2];

    auto fetch = [&](int k0) {
#pragma unroll
        for (int jj = 0; jj < 2; jj++) {
            int r = srow + 64 * jj;
            int gr = row0 + r;
            ar[jj] = (gr < M) ? *(const uint4*)(Ah + (size_t)gr * K + k0 + 8 * sq)
                              : make_uint4(0, 0, 0, 0);
            br[jj] = *(const uint4*)(Wt + (size_t)(col0 + r) * K + k0 + 8 * sq);
        }
    };
    auto scat = [&](uint32_t* sA, uint32_t* sB) {
#pragma unroll
        for (int jj = 0; jj < 2; jj++) {
            int r = srow + 64 * jj;
            *(uint4*)(sA + r * ROWW + 4 * sq) = ar[jj];
            *(uint4*)(sB + r * ROWW + 4 * sq) = br[jj];
        }
    };

    fetch(0);
    scat(dsm, dsm + TILE_WORDS);
    __syncthreads();

    for (int ch = 0; ch < nch; ch++) {
        const int s = ch & 1;
        if (ch + 1 < nch) fetch((ch + 1) << 5);

        uint32_t sA = sbase + s * 2 * TILE_WORDS * 4;
        gemm_compute_chunk(sA, sA + TILE_WORDS * 4, wm, wn, lane, acc);

        if (ch + 1 < nch) {
            uint32_t* nA = dsm + (s ^ 1) * 2 * TILE_WORDS;
            scat(nA, nA + TILE_WORDS);
        }
        __syncthreads();
    }

    gemm_epilogue<C_HALF>(Cv, bias, M, row0, col0, wm, wn, lane, acc, doStats);
}

// ---------------- tf32 mma head (K=256, Nc=40, padded to 64) ----------------
#define HEAD_SMEM 49152
__global__ __launch_bounds__(256, 2) void head_mma_k(
    const float* __restrict__ A, const float* __restrict__ W,
    const float* __restrict__ bias, float* __restrict__ C, int M) {
    extern __shared__ uint32_t hsm[];
    uint32_t* sAb = hsm;
    uint32_t* sBb = hsm + 8192;

    const int tid = threadIdx.x;
    const int lane = tid & 31;
    const int wid = tid >> 5;
    const int wm = wid >> 2, wn = wid & 3;
    const int row0 = blockIdx.y * 128;

    const int c4 = (tid & 7) * 4;
    const int rbase = tid >> 3;
    const int bn4 = (tid & 15) * 4;
    const int bkbase = tid >> 4;

    float acc[4][2][4];
#pragma unroll
    for (int i = 0; i < 4; i++)
#pragma unroll
        for (int j = 0; j < 2; j++)
#pragma unroll
            for (int t = 0; t < 4; t++) acc[i][j][t] = 0.0f;

    float4 av[4], bv[2];

    auto fetchH = [&](int k0) {
#pragma unroll
        for (int j = 0; j < 4; j++) {
            int gr = row0 + rbase + 32 * j;
            av[j] = (gr < M) ? *(const float4*)(A + (size_t)gr * 256 + k0 + c4)
                             : make_float4(0.f, 0.f, 0.f, 0.f);
        }
#pragma unroll
        for (int j = 0; j < 2; j++) {
            int k = bkbase + 16 * j;
            bv[j] = (bn4 < CLS) ? *(const float4*)(W + (size_t)(k0 + k) * CLS + bn4)
                                : make_float4(0.f, 0.f, 0.f, 0.f);
        }
    };
    auto scatH = [&](uint32_t* sa, uint32_t* sb) {
#pragma unroll
        for (int j = 0; j < 4; j++) {
            int r = rbase + 32 * j;
            int r16 = r & 15, mt = r >> 4;
            float vals[4] = {av[j].x, av[j].y, av[j].z, av[j].w};
#pragma unroll
            for (int t = 0; t < 4; t++) {
                int c = c4 + t;
                int kk = c >> 3, c8 = c & 7;
                int ln = (r16 & 7) * 4 + (c8 & 3);
                int sl = (r16 >> 3) | ((c8 >> 2) << 1);
                int tile = kk * 8 + mt;
                int lp = ln ^ ((tile >> 3) << 2);
                sa[(tile * 32 + lp) * 4 + sl] = tf32r(vals[t]);
            }
        }
#pragma unroll
        for (int j = 0; j < 2; j++) {
            int k = bkbase + 16 * j;
            int kk = k >> 3, k8 = k & 7;
            int sl = k8 >> 2, l4 = k8 & 3;
            float vals[4] = {bv[j].x, bv[j].y, bv[j].z, bv[j].w};
#pragma unroll
            for (int t = 0; t < 4; t++) {
                int n = bn4 + t;
                int nt = n >> 3, n8 = n & 7;
                int tile = kk * 8 + nt;
                int ln = n8 * 4 + l4;
                int lp = ln ^ ((tile & 7) << 2);
                sb[(tile * 32 + lp) * 2 + sl] = tf32r(vals[t]);
            }
        }
    };

    fetchH(0);
    scatH(sAb, sBb);
    __syncthreads();

#pragma unroll 1
    for (int ch = 0; ch < 8; ch++) {
        const int s = ch & 1;
        if (ch + 1 < 8) fetchH((ch + 1) << 5);
        const uint32_t* sa = sAb + s * 4096;
        const uint32_t* sb = sBb + s * 2048;
#pragma unroll
        for (int kk = 0; kk < 4; kk++) {
            uint32_t af[4][4];
            uint32_t bf[2][2];
#pragma unroll
            for (int im = 0; im < 4; im++) {
                int tile = kk * 8 + wm * 4 + im;
                int lp = lane ^ ((tile >> 3) << 2);
                uint4 u = *(const uint4*)(sa + (tile * 32 + lp) * 4);
                af[im][0] = u.x; af[im][1] = u.y; af[im][2] = u.z; af[im][3] = u.w;
            }
#pragma unroll
            for (int in = 0; in < 2; in++) {
                int tile = kk * 8 + wn * 2 + in;
                int lp = lane ^ ((tile & 7) << 2);
                uint2 u = *(const uint2*)(sb + (tile * 32 + lp) * 2);
                bf[in][0] = u.x; bf[in][1] = u.y;
            }
#pragma unroll
            for (int im = 0; im < 4; im++)
#pragma unroll
                for (int in = 0; in < 2; in++)
                    asm volatile(
                        "mma.sync.aligned.m16n8k8.row.col.f32.tf32.tf32.f32 "
                        "{%0,%1,%2,%3}, {%4,%5,%6,%7}, {%8,%9}, {%0,%1,%2,%3};"
                        : "+f"(acc[im][in][0]), "+f"(acc[im][in][1]),
                          "+f"(acc[im][in][2]), "+f"(acc[im][in][3])
                        : "r"(af[im][0]), "r"(af[im][1]), "r"(af[im][2]), "r"(af[im][3]),
                          "r"(bf[in][0]), "r"(bf[in][1]));
        }
        if (ch + 1 < 8) scatH(sAb + (s ^ 1) * 4096, sBb + (s ^ 1) * 2048);
        __syncthreads();
    }

#pragma unroll
    for (int im = 0; im < 4; im++) {
        int rl = row0 + wm * 64 + im * 16 + (lane >> 2);
        int rh = rl + 8;
#pragma unroll
        for (int in = 0; in < 2; in++) {
            int cc = wn * 16 + in * 8 + (lane & 3) * 2;
            if (cc >= CLS) continue;
            float b0 = bias[cc], b1 = bias[cc + 1];
            if (rl < M) {
                float2 v = make_float2(acc[im][in][0] + b0, acc[im][in][1] + b1);
                *(float2*)(C + (size_t)rl * CLS + cc) = v;
            }
            if (rh < M) {
                float2 v = make_float2(acc[im][in][2] + b0, acc[im][in][3] + b1);
                *(float2*)(C + (size_t)rh * CLS + cc) = v;
            }
        }
    }
}

// ---------------- CSR build ----------------
__global__ void zero_k(float* __restrict__ p, int n) {
    int i = blockIdx.x * blockDim.x + threadIdx.x;
    if (i < n) p[i] = 0.0f;
}
__global__ void zeroi_k(int* __restrict__ p, int n) {
    int i = blockIdx.x * blockDim.x + threadIdx.x;
    if (i < n) p[i] = 0;
}
__global__ void zstats_k() {
    int i = threadIdx.x;  // <<<1, D>>>
    g_sum[i] = 0.0f;
    g_sumsq[i] = 0.0f;
}

__global__ void deg_k(const int* __restrict__ src, const int* __restrict__ dst, int E) {
    int e = blockIdx.x * blockDim.x + threadIdx.x;
    if (e < E) {
        atomicAdd(&g_degout[src[e]], 1.0f);
        atomicAdd(&g_degin[dst[e]], 1.0f);
        atomicAdd(&g_cnt[dst[e]], 1);
    }
}

__global__ void norm_k(int n) {
    int i = blockIdx.x * blockDim.x + threadIdx.x;
    if (i < n) {
        g_ns[i] = rsqrtf(fmaxf(g_degout[i], 1.0f));
        g_nd[i] = rsqrtf(fmaxf(g_degin[i], 1.0f));
    }
}

__global__ void scan1_k(int Nn) {
    __shared__ int sh[256];
    int i = blockIdx.x * 256 + threadIdx.x;
    int v = (i < Nn) ? g_cnt[i] : 0;
    sh[threadIdx.x] = v;
    __syncthreads();
    for (int off = 1; off < 256; off <<= 1) {
        int t = (threadIdx.x >= off) ? sh[threadIdx.x - off] : 0;
        __syncthreads();
        sh[threadIdx.x] += t;
        __syncthreads();
    }
    if (i < Nn) g_rowptr[i] = sh[threadIdx.x] - v;
    if (threadIdx.x == 255) g_bsum[blockIdx.x] = sh[255];
}

__global__ void scan2_k(int nb) {
    __shared__ int sh[256];
    int v = (threadIdx.x < nb) ? g_bsum[threadIdx.x] : 0;
    sh[threadIdx.x] = v;
    __syncthreads();
    for (int off = 1; off < 256; off <<= 1) {
        int t = (threadIdx.x >= off) ? sh[threadIdx.x - off] : 0;
        __syncthreads();
        sh[threadIdx.x] += t;
        __syncthreads();
    }
    g_boff[threadIdx.x] = sh[threadIdx.x] - v;
}

__global__ void scan3_k(int Nn, int E) {
    int i = blockIdx.x * 256 + threadIdx.x;
    if (i < Nn) {
        int r = g_rowptr[i] + g_boff[blockIdx.x];
        g_rowptr[i] = r;
        g_cursor[i] = r;
    }
    if (i == 0) g_rowptr[Nn] = E;
}

__global__ void fill_k(const int* __restrict__ src, const int* __restrict__ dst, int E) {
    int e = blockIdx.x * blockDim.x + threadIdx.x;
    if (e < E) {
        int pos = atomicAdd(&g_cursor[dst[e]], 1);
        g_esrc[pos] = src[e];
    }
}

// ---------------- CSR gather SpMM (fp16 in/out, fp32 accum, 2x unroll) ----------
__global__ __launch_bounds__(256) void spmmh_k(const __half* __restrict__ X,
                                               __half* __restrict__ Mo, int Nn) {
    int node = blockIdx.x * 4 + (threadIdx.x >> 6);
    if (node >= Nn) return;
    int c0 = (threadIdx.x & 63) * 4;
    int beg = g_rowptr[node], end = g_rowptr[node + 1];
    float a0 = 0.f, a1 = 0.f, a2 = 0.f, a3 = 0.f;
    float b0 = 0.f, b1 = 0.f, b2 = 0.f, b3 = 0.f;
    int j = beg;
    for (; j + 2 <= end; j += 2) {
        int s0 = g_esrc[j], s1 = g_esrc[j + 1];
        float c0s = g_ns[s0], c1s = g_ns[s1];
        uint2 u0 = *(const uint2*)(X + (size_t)s0 * D + c0);
        uint2 u1 = *(const uint2*)(X + (size_t)s1 * D + c0);
        float2 f00 = __half22float2(*(__half2*)&u0.x);
        float2 f01 = __half22float2(*(__half2*)&u0.y);
        float2 f10 = __half22float2(*(__half2*)&u1.x);
        float2 f11 = __half22float2(*(__half2*)&u1.y);
        a0 += f00.x * c0s; a1 += f00.y * c0s; a2 += f01.x * c0s; a3 += f01.y * c0s;
        b0 += f10.x * c1s; b1 += f10.y * c1s; b2 += f11.x * c1s; b3 += f11.y * c1s;
    }
    if (j < end) {
        int s0 = g_esrc[j];
        float c0s = g_ns[s0];
        uint2 u0 = *(const uint2*)(X + (size_t)s0 * D + c0);
        float2 f00 = __half22float2(*(__half2*)&u0.x);
        float2 f01 = __half22float2(*(__half2*)&u0.y);
        a0 += f00.x * c0s; a1 += f00.y * c0s; a2 += f01.x * c0s; a3 += f01.y * c0s;
    }
    a0 += b0; a1 += b1; a2 += b2; a3 += b3;
    float nd = g_nd[node];
    __half2 o0 = __floats2half2_rn(a0 * nd, a1 * nd);
    __half2 o1 = __floats2half2_rn(a2 * nd, a3 * nd);
    uint2 o;
    o.x = *(uint32_t*)&o0;
    o.y = *(uint32_t*)&o1;
    *(uint2*)(Mo + (size_t)node * D + c0) = o;
}

// ---------------- batchnorm finalize + apply (fp16) ----------------
__global__ void bnfin_k(const float* __restrict__ gamma, const float* __restrict__ beta,
                        float invN) {
    int c = threadIdx.x;
    float mean = g_sum[c] * invN;
    float var = g_sumsq[c] * invN - mean * mean;
    float sc = gamma[c] * rsqrtf(var + 1e-5f);
    g_scale[c] = sc;
    g_shift[c] = beta[c] - mean * sc;
}

__device__ __forceinline__ float elu1(float v) { return v > 0.0f ? v : expm1f(v); }

__global__ void bnapplyh_k(uint4* __restrict__ X, int n8) {
    int i = blockIdx.x * blockDim.x + threadIdx.x;
    if (i >= n8) return;
    int c = (i & 31) * 8;
    uint4 u = X[i];
    __half2* h = (__half2*)&u;
#pragma unroll
    for (int t = 0; t < 4; t++) {
        float2 f = __half22float2(h[t]);
        f.x = elu1(f.x * g_scale[c + 2 * t] + g_shift[c + 2 * t]);
        f.y = elu1(f.y * g_scale[c + 2 * t + 1] + g_shift[c + 2 * t + 1]);
        h[t] = __floats2half2_rn(f.x, f.y);
    }
    X[i] = u;
}

// ---------------- host orchestration ----------------
static inline int cdiv(int a, int b) { return (a + b - 1) / b; }

extern "C" void kernel_launch(void* const* d_in, const int* in_sizes, int n_in,
                              void* d_out, int out_size) {
    const float* feat  = (const float*)d_in[0];
    const int*   src   = (const int*)d_in[1];
    const int*   dst   = (const int*)d_in[2];
    const float* W_fc  = (const float*)d_in[3];
    const float* b_fc  = (const float*)d_in[4];
    const float* W1    = (const float*)d_in[5];
    const float* b1    = (const float*)d_in[6];
    const float* W2    = (const float*)d_in[7];
    const float* b2    = (const float*)d_in[8];
    const float* W3    = (const float*)d_in[9];
    const float* b3    = (const float*)d_in[10];
    const float* gamma = (const float*)d_in[11];
    const float* beta  = (const float*)d_in[12];
    const float* W_lin = (const float*)d_in[13];
    const float* b_lin = (const float*)d_in[14];
    float* out = (float*)d_out;

    int N = in_sizes[0] / F;  // 50000
    int E = in_sizes[1];      // 300000

    cudaFuncSetAttribute(h_gemm_ca, cudaFuncAttributeMaxDynamicSharedMemorySize, GEMM_SMEM_CA);
    cudaFuncSetAttribute(h_gemm_rb<1>, cudaFuncAttributeMaxDynamicSharedMemorySize, GEMM_SMEM_RB);
    cudaFuncSetAttribute(h_gemm_rb<0>, cudaFuncAttributeMaxDynamicSharedMemorySize, GEMM_SMEM_RB);
    cudaFuncSetAttribute(head_mma_k, cudaFuncAttributeMaxDynamicSharedMemorySize, HEAD_SMEM);

    __half *pFh, *pXh, *pYh, *pMh, *pWth;
    float *pDegO, *pDegI;
    int *pCnt;
    cudaGetSymbolAddress((void**)&pFh, g_Fh);
    cudaGetSymbolAddress((void**)&pXh, g_Xh);
    cudaGetSymbolAddress((void**)&pYh, g_Yh);
    cudaGetSymbolAddress((void**)&pMh, g_Mh);
    cudaGetSymbolAddress((void**)&pWth, g_Wth);
    cudaGetSymbolAddress((void**)&pDegO, g_degout);
    cudaGetSymbolAddress((void**)&pDegI, g_degin);
    cudaGetSymbolAddress((void**)&pCnt, g_cnt);

    const int ND = N * D;
    const int TB = 256;
    const int nb = cdiv(N, 256);
    const dim3 ggrid(2, cdiv(N, 128));
    const dim3 hgrid(1, cdiv(N, 128));
    const dim3 tthr(32, 8);
    const int sgrid = cdiv(N, 4);

    // ---- FC path first so the FC GEMM is launch #4 for ncu ----
    f2h_k<<<cdiv(N * F / 4, TB), TB>>>((const float4*)feat, (uint2*)pFh, N * F / 4);  // 1
    wt_k<<<dim3(F / 32, 8), tthr>>>(W_fc, pWth, F);                                   // 2
    zero_k<<<cdiv(N, TB), TB>>>(pDegO, N);                                            // 3
    h_gemm_ca<<<ggrid, 256, GEMM_SMEM_CA>>>(pFh, pWth, b_fc, pXh, N, F, 0);           // 4 (profiled)

    // ---- degree norms + CSR build ----
    zero_k<<<cdiv(N, TB), TB>>>(pDegI, N);
    zeroi_k<<<cdiv(N, TB), TB>>>(pCnt, N);
    deg_k<<<cdiv(E, TB), TB>>>(src, dst, E);
    norm_k<<<cdiv(N, TB), TB>>>(N);
    scan1_k<<<nb, 256>>>(N);
    scan2_k<<<1, 256>>>(nb);
    scan3_k<<<nb, 256>>>(N, E);
    fill_k<<<cdiv(E, TB), TB>>>(src, dst, E);

    // ---- layer 1 ----
    spmmh_k<<<sgrid, 256>>>(pXh, pMh, N);
    wt_k<<<dim3(D / 32, 8), tthr>>>(W1, pWth, D);
    zstats_k<<<1, D>>>();
    h_gemm_rb<1><<<ggrid, 256, GEMM_SMEM_RB>>>(pMh, pWth, b1, pYh, N, D, 1);
    bnfin_k<<<1, D>>>(gamma, beta, 1.0f / (float)N);
    bnapplyh_k<<<cdiv(ND / 8, TB), TB>>>((uint4*)pYh, ND / 8);

    // ---- layer 2 ----
    spmmh_k<<<sgrid, 256>>>(pYh, pMh, N);
    wt_k<<<dim3(D / 32, 8), tthr>>>(W2, pWth, D);
    zstats_k<<<1, D>>>();
    h_gemm_rb<1><<<ggrid, 256, GEMM_SMEM_RB>>>(pMh, pWth, b2, pXh, N, D, 1);
    bnfin_k<<<1, D>>>(gamma, beta, 1.0f / (float)N);
    bnapplyh_k<<<cdiv(ND / 8, TB), TB>>>((uint4*)pXh, ND / 8);

    // ---- layer 3: gconv -> out[0 : N*D] fp32 ----
    spmmh_k<<<sgrid, 256>>>(pXh, pMh, N);
    wt_k<<<dim3(D / 32, 8), tthr>>>(W3, pWth, D);
    h_gemm_rb<0><<<ggrid, 256, GEMM_SMEM_RB>>>(pMh, pWth, b3, out, N, D, 0);

    // ---- head: logits = x @ W_lin + b_lin ----
    head_mma_k<<<hgrid, 256, HEAD_SMEM>>>(out, W_lin, b_lin, out + (size_t)N * D, N);
}

// round 16
// speedup vs baseline: 1.0250x; 1.0250x over previous
#include <cuda_runtime.h>
#include <cuda_fp16.h>
#include <cstdint>
#include <math.h>

#define D 256
#define F 1024
#define CLS 40
#define NMAX 50000
#define EMAX 300000
#define ROWW 20  // padded words per 32-half tile row (bank-conflict-free bijection)

// ---------------- scratch (static device memory; no allocations) ----------------
__device__ __half g_Fh[NMAX * F];     // fp16 copy of feat
__device__ __half g_Xh[NMAX * D];
__device__ __half g_Yh[NMAX * D];
__device__ __half g_Mh[NMAX * D];
__device__ __half g_Wth[256 * 1024];  // fp16 Wt: FC uses all; layers use +l*65536
__device__ float g_degout[NMAX];
__device__ float g_degin[NMAX];
__device__ float g_ns[NMAX];
__device__ float g_nd[NMAX];
__device__ float g_sum[2 * D];        // two stat sets (layer1, layer2)
__device__ float g_sumsq[2 * D];
__device__ float g_scale[D];
__device__ float g_shift[D];
// CSR by dst
__device__ int g_cnt[NMAX];
__device__ int g_rowptr[NMAX + 1];
__device__ int g_cursor[NMAX];
__device__ int g_esrc[EMAX];
__device__ int g_bsum[256];
__device__ int g_boff[256];

__device__ __forceinline__ uint32_t tf32r(float x) {
    uint32_t r;
    asm("cvt.rna.tf32.f32 %0, %1;" : "=r"(r) : "f"(x));
    return r;
}
__device__ __forceinline__ uint32_t h2pack(float lo, float hi) {
    __half2 h = __floats2half2_rn(lo, hi);
    return *(uint32_t*)&h;
}

// ---------------- feat fp32 -> fp16 ----------------
__global__ void f2h_k(const float4* __restrict__ in, uint2* __restrict__ out, int n4) {
    int i = blockIdx.x * blockDim.x + threadIdx.x;
    if (i >= n4) return;
    float4 v = in[i];
    uint2 o;
    o.x = h2pack(v.x, v.y);
    o.y = h2pack(v.z, v.w);
    out[i] = o;
}

// ---------------- weight transpose+convert: W[K][256] fp32 -> Wt[256][K] fp16 ----
__global__ void wt_k(const float* __restrict__ W, __half* __restrict__ Wt, int K) {
    __shared__ float t[32][33];
    int k0 = blockIdx.x * 32, n0 = blockIdx.y * 32;
    int x = threadIdx.x, y = threadIdx.y;  // 32 x 8
    for (int j = y; j < 32; j += 8) t[j][x] = W[(size_t)(k0 + j) * 256 + n0 + x];
    __syncthreads();
    for (int j = y; j < 32; j += 8)
        Wt[(size_t)(n0 + j) * K + k0 + x] = __float2half(t[x][j]);
}

// batched: 3 D-layer weights (K=256) -> g_Wth + z*65536
__global__ void wt3_k(const float* __restrict__ W1, const float* __restrict__ W2,
                      const float* __restrict__ W3) {
    __shared__ float t[32][33];
    const float* W = (blockIdx.z == 0) ? W1 : (blockIdx.z == 1) ? W2 : W3;
    __half* Wt = g_Wth + (size_t)blockIdx.z * 65536;
    int k0 = blockIdx.x * 32, n0 = blockIdx.y * 32;
    int x = threadIdx.x, y = threadIdx.y;
    for (int j = y; j < 32; j += 8) t[j][x] = W[(size_t)(k0 + j) * 256 + n0 + x];
    __syncthreads();
    for (int j = y; j < 32; j += 8)
        Wt[(size_t)(n0 + j) * 256 + k0 + x] = __float2half(t[x][j]);
}

// ================= shared GEMM building blocks =================
#define TILE_WORDS (128 * ROWW)  // 2560 words per A or B buffer

// ldmatrix-based chunk compute (used by the long-K FC kernel — measured win there).
__device__ __forceinline__ void gemm_compute_chunk_ldm(
    uint32_t sA, uint32_t sB, int wm, int wn, int lane, float (&acc)[4][4][4]) {
    const int lr = lane & 15;
    const int lc = lane >> 4;
#pragma unroll
    for (int kk = 0; kk < 2; kk++) {
        uint32_t afr[4][4];
        uint32_t bfr[4][2];
        const uint32_t coff = (kk * 16 + lc * 8) * 2;
#pragma unroll
        for (int im = 0; im < 4; im++) {
            int m = wm * 64 + im * 16 + lr;
            uint32_t addr = sA + m * (ROWW * 4) + coff;
            asm volatile(
                "ldmatrix.sync.aligned.m8n8.x4.shared.b16 {%0,%1,%2,%3}, [%4];"
                : "=r"(afr[im][0]), "=r"(afr[im][1]),
                  "=r"(afr[im][2]), "=r"(afr[im][3])
                : "r"(addr));
        }
#pragma unroll
        for (int ib = 0; ib < 2; ib++) {
            int n = wn * 32 + ib * 16 + lr;
            uint32_t addr = sB + n * (ROWW * 4) + coff;
            uint32_t r0, r1, r2, r3;
            asm volatile(
                "ldmatrix.sync.aligned.m8n8.x4.shared.b16 {%0,%1,%2,%3}, [%4];"
                : "=r"(r0), "=r"(r1), "=r"(r2), "=r"(r3)
                : "r"(addr));
            bfr[2 * ib][0] = r0; bfr[2 * ib + 1][0] = r1;
            bfr[2 * ib][1] = r2; bfr[2 * ib + 1][1] = r3;
        }
#pragma unroll
        for (int im = 0; im < 4; im++)
#pragma unroll
            for (int in = 0; in < 4; in++)
                asm volatile(
                    "mma.sync.aligned.m16n8k16.row.col.f32.f16.f16.f32 "
                    "{%0,%1,%2,%3}, {%4,%5,%6,%7}, {%8,%9}, {%0,%1,%2,%3};"
                    : "+f"(acc[im][in][0]), "+f"(acc[im][in][1]),
                      "+f"(acc[im][in][2]), "+f"(acc[im][in][3])
                    : "r"(afr[im][0]), "r"(afr[im][1]), "r"(afr[im][2]), "r"(afr[im][3]),
                      "r"(bfr[in][0]), "r"(bfr[in][1]));
    }
}

// Shared epilogue: bias, store (fp16 or fp32), optional fused column stats.
template <int C_HALF>
__device__ __forceinline__ void gemm_epilogue(
    void* Cv, const float* bias, int M, int row0, int col0,
    int wm, int wn, int lane, float (&acc)[4][4][4],
    float* psum, float* psumsq) {
    float s_[4][2] = {{0.f}}, q_[4][2] = {{0.f}};
#pragma unroll
    for (int im = 0; im < 4; im++) {
        int rl = row0 + wm * 64 + im * 16 + (lane >> 2);
        int rh = rl + 8;
        bool vl = rl < M, vh = rh < M;
#pragma unroll
        for (int in = 0; in < 4; in++) {
            int cc = col0 + wn * 32 + in * 8 + (lane & 3) * 2;
            float b0 = bias[cc], b1 = bias[cc + 1];
            float v0 = acc[im][in][0] + b0, v1 = acc[im][in][1] + b1;
            float v2 = acc[im][in][2] + b0, v3 = acc[im][in][3] + b1;
            if (vl) {
                if (C_HALF)
                    *(__half2*)((__half*)Cv + (size_t)rl * 256 + cc) = __floats2half2_rn(v0, v1);
                else
                    *(float2*)((float*)Cv + (size_t)rl * 256 + cc) = make_float2(v0, v1);
                s_[in][0] += v0; q_[in][0] += v0 * v0;
                s_[in][1] += v1; q_[in][1] += v1 * v1;
            }
            if (vh) {
                if (C_HALF)
                    *(__half2*)((__half*)Cv + (size_t)rh * 256 + cc) = __floats2half2_rn(v2, v3);
                else
                    *(float2*)((float*)Cv + (size_t)rh * 256 + cc) = make_float2(v2, v3);
                s_[in][0] += v2; q_[in][0] += v2 * v2;
                s_[in][1] += v3; q_[in][1] += v3 * v3;
            }
        }
    }
    if (psum != nullptr) {
#pragma unroll
        for (int in = 0; in < 4; in++)
#pragma unroll
            for (int t = 0; t < 2; t++) {
#pragma unroll
                for (int m = 4; m < 32; m <<= 1) {
                    s_[in][t] += __shfl_xor_sync(0xFFFFFFFF, s_[in][t], m);
                    q_[in][t] += __shfl_xor_sync(0xFFFFFFFF, q_[in][t], m);
                }
            }
        if ((lane >> 2) == 0) {
#pragma unroll
            for (int in = 0; in < 4; in++)
#pragma unroll
                for (int t = 0; t < 2; t++) {
                    int cc = col0 + wn * 32 + in * 8 + (lane & 3) * 2 + t;
                    atomicAdd(&psum[cc], s_[in][t]);
                    atomicAdd(&psumsq[cc], q_[in][t]);
                }
        }
    }
}

// ---------------- FC GEMM: cp.async 3-stage + ldmatrix (long K) ----------------
#define NSTAGE 3
#define GEMM_SMEM_CA (NSTAGE * 2 * TILE_WORDS * 4)  // 61440 B

__global__ __launch_bounds__(256, 2) void h_gemm_ca(
    const __half* __restrict__ Ah, const __half* __restrict__ Wt,
    const float* __restrict__ bias, void* __restrict__ Cv,
    int M, int K) {
    extern __shared__ uint32_t dsm[];
    const uint32_t sbase = (uint32_t)__cvta_generic_to_shared(dsm);

    const int tid = threadIdx.x;
    const int lane = tid & 31;
    const int wid = tid >> 5;
    const int wm = wid >> 2, wn = wid & 3;
    const int row0 = blockIdx.y * 128;
    const int col0 = blockIdx.x * 128;

    float acc[4][4][4];
#pragma unroll
    for (int i = 0; i < 4; i++)
#pragma unroll
        for (int j = 0; j < 4; j++)
#pragma unroll
            for (int t = 0; t < 4; t++) acc[i][j][t] = 0.0f;

    const int nch = K >> 5;

    auto issue = [&](int buf, int k0) {
        uint32_t sA = sbase + buf * 2 * TILE_WORDS * 4;
        uint32_t sB = sA + TILE_WORDS * 4;
#pragma unroll
        for (int j = 0; j < 2; j++) {
            int id = tid + 256 * j;
            int r = id >> 2, sq = id & 3;
            uint32_t soff = (r * ROWW + 4 * sq) * 4;
            int gr = row0 + r;
            int grc = gr < M ? gr : 0;
            const __half* ga = Ah + (size_t)grc * K + k0 + 8 * sq;
            int sz = (gr < M) ? 16 : 0;
            asm volatile("cp.async.cg.shared.global [%0], [%1], 16, %2;"
                         :: "r"(sA + soff), "l"(ga), "r"(sz) : "memory");
            const __half* gb = Wt + (size_t)(col0 + r) * K + k0 + 8 * sq;
            asm volatile("cp.async.cg.shared.global [%0], [%1], 16;"
                         :: "r"(sB + soff), "l"(gb) : "memory");
        }
        asm volatile("cp.async.commit_group;" ::: "memory");
    };

    issue(0, 0);
    issue(1, 32);

    for (int ch = 0; ch < nch; ch++) {
        const int s = ch % 3;
        if (ch == nch - 1)
            asm volatile("cp.async.wait_group 0;" ::: "memory");
        else
            asm volatile("cp.async.wait_group 1;" ::: "memory");
        __syncthreads();
        if (ch + 2 < nch) issue((ch + 2) % 3, (ch + 2) * 32);
        uint32_t sA = sbase + s * 2 * TILE_WORDS * 4;
        gemm_compute_chunk_ldm(sA, sA + TILE_WORDS * 4, wm, wn, lane, acc);
    }

    gemm_epilogue<1>(Cv, bias, M, row0, col0, wm, wn, lane, acc, nullptr, nullptr);
}

// ---------------- D-GEMM: R11 register double-buffer + scalar fragment LDS ----------
#define GEMM_SMEM_RB (4 * TILE_WORDS * 4)  // 40960 B

template <int C_HALF>
__global__ __launch_bounds__(256, 2) void h_gemm_rb(
    const __half* __restrict__ Ah, const __half* __restrict__ Wt,
    const float* __restrict__ bias, void* __restrict__ Cv,
    int M, int K, float* psum, float* psumsq) {
    extern __shared__ uint32_t dsm[];

    const int tid = threadIdx.x;
    const int lane = tid & 31;
    const int wid = tid >> 5;
    const int wm = wid >> 2, wn = wid & 3;
    const int row0 = blockIdx.y * 128;
    const int col0 = blockIdx.x * 128;

    const int srow = tid >> 2;  // 0..63
    const int sq = tid & 3;

    float acc[4][4][4];
#pragma unroll
    for (int i = 0; i < 4; i++)
#pragma unroll
        for (int j = 0; j < 4; j++)
#pragma unroll
            for (int t = 0; t < 4; t++) acc[i][j][t] = 0.0f;

    const int nch = K >> 5;
    uint4 ar[2], br[2];

    auto fetch = [&](int k0) {
#pragma unroll
        for (int jj = 0; jj < 2; jj++) {
            int r = srow + 64 * jj;
            int gr = row0 + r;
            ar[jj] = (gr < M) ? *(const uint4*)(Ah + (size_t)gr * K + k0 + 8 * sq)
                              : make_uint4(0, 0, 0, 0);
            br[jj] = *(const uint4*)(Wt + (size_t)(col0 + r) * K + k0 + 8 * sq);
        }
    };
    auto scat = [&](uint32_t* sA, uint32_t* sB) {
#pragma unroll
        for (int jj = 0; jj < 2; jj++) {
            int r = srow + 64 * jj;
            *(uint4*)(sA + r * ROWW + 4 * sq) = ar[jj];
            *(uint4*)(sB + r * ROWW + 4 * sq) = br[jj];
        }
    };

    fetch(0);
    scat(dsm, dsm + TILE_WORDS);
    __syncthreads();

    const int lq = lane & 3;
    const int lr = lane >> 2;

    for (int ch = 0; ch < nch; ch++) {
        const int s = ch & 1;
        if (ch + 1 < nch) fetch((ch + 1) << 5);

        const uint32_t* sA = dsm + s * 2 * TILE_WORDS;
        const uint32_t* sB = sA + TILE_WORDS;
#pragma unroll
        for (int kk = 0; kk < 2; kk++) {
            uint32_t afr[4][4];
            uint32_t bfr[4][2];
#pragma unroll
            for (int im = 0; im < 4; im++) {
                int m = wm * 64 + im * 16 + lr;
                const uint32_t* p0 = sA + m * ROWW + kk * 8 + lq;
                const uint32_t* p1 = sA + (m + 8) * ROWW + kk * 8 + lq;
                afr[im][0] = p0[0];
                afr[im][1] = p1[0];
                afr[im][2] = p0[4];
                afr[im][3] = p1[4];
            }
#pragma unroll
            for (int in = 0; in < 4; in++) {
                int n = wn * 32 + in * 8 + lr;
                const uint32_t* p = sB + n * ROWW + kk * 8 + lq;
                bfr[in][0] = p[0];
                bfr[in][1] = p[4];
            }
#pragma unroll
            for (int im = 0; im < 4; im++)
#pragma unroll
                for (int in = 0; in < 4; in++)
                    asm volatile(
                        "mma.sync.aligned.m16n8k16.row.col.f32.f16.f16.f32 "
                        "{%0,%1,%2,%3}, {%4,%5,%6,%7}, {%8,%9}, {%0,%1,%2,%3};"
                        : "+f"(acc[im][in][0]), "+f"(acc[im][in][1]),
                          "+f"(acc[im][in][2]), "+f"(acc[im][in][3])
                        : "r"(afr[im][0]), "r"(afr[im][1]), "r"(afr[im][2]), "r"(afr[im][3]),
                          "r"(bfr[in][0]), "r"(bfr[in][1]));
        }
        if (ch + 1 < nch) {
            uint32_t* nA = dsm + (s ^ 1) * 2 * TILE_WORDS;
            scat(nA, nA + TILE_WORDS);
        }
        __syncthreads();
    }

    gemm_epilogue<C_HALF>(Cv, bias, M, row0, col0, wm, wn, lane, acc, psum, psumsq);
}

// ---------------- tf32 mma head (K=256, Nc=40, padded to 64) ----------------
#define HEAD_SMEM 49152
__global__ __launch_bounds__(256, 2) void head_mma_k(
    const float* __restrict__ A, const float* __restrict__ W,
    const float* __restrict__ bias, float* __restrict__ C, int M) {
    extern __shared__ uint32_t hsm[];
    uint32_t* sAb = hsm;
    uint32_t* sBb = hsm + 8192;

    const int tid = threadIdx.x;
    const int lane = tid & 31;
    const int wid = tid >> 5;
    const int wm = wid >> 2, wn = wid & 3;
    const int row0 = blockIdx.y * 128;

    const int c4 = (tid & 7) * 4;
    const int rbase = tid >> 3;
    const int bn4 = (tid & 15) * 4;
    const int bkbase = tid >> 4;

    float acc[4][2][4];
#pragma unroll
    for (int i = 0; i < 4; i++)
#pragma unroll
        for (int j = 0; j < 2; j++)
#pragma unroll
            for (int t = 0; t < 4; t++) acc[i][j][t] = 0.0f;

    float4 av[4], bv[2];

    auto fetchH = [&](int k0) {
#pragma unroll
        for (int j = 0; j < 4; j++) {
            int gr = row0 + rbase + 32 * j;
            av[j] = (gr < M) ? *(const float4*)(A + (size_t)gr * 256 + k0 + c4)
                             : make_float4(0.f, 0.f, 0.f, 0.f);
        }
#pragma unroll
        for (int j = 0; j < 2; j++) {
            int k = bkbase + 16 * j;
            bv[j] = (bn4 < CLS) ? *(const float4*)(W + (size_t)(k0 + k) * CLS + bn4)
                                : make_float4(0.f, 0.f, 0.f, 0.f);
        }
    };
    auto scatH = [&](uint32_t* sa, uint32_t* sb) {
#pragma unroll
        for (int j = 0; j < 4; j++) {
            int r = rbase + 32 * j;
            int r16 = r & 15, mt = r >> 4;
            float vals[4] = {av[j].x, av[j].y, av[j].z, av[j].w};
#pragma unroll
            for (int t = 0; t < 4; t++) {
                int c = c4 + t;
                int kk = c >> 3, c8 = c & 7;
                int ln = (r16 & 7) * 4 + (c8 & 3);
                int sl = (r16 >> 3) | ((c8 >> 2) << 1);
                int tile = kk * 8 + mt;
                int lp = ln ^ ((tile >> 3) << 2);
                sa[(tile * 32 + lp) * 4 + sl] = tf32r(vals[t]);
            }
        }
#pragma unroll
        for (int j = 0; j < 2; j++) {
            int k = bkbase + 16 * j;
            int kk = k >> 3, k8 = k & 7;
            int sl = k8 >> 2, l4 = k8 & 3;
            float vals[4] = {bv[j].x, bv[j].y, bv[j].z, bv[j].w};
#pragma unroll
            for (int t = 0; t < 4; t++) {
                int n = bn4 + t;
                int nt = n >> 3, n8 = n & 7;
                int tile = kk * 8 + nt;
                int ln = n8 * 4 + l4;
                int lp = ln ^ ((tile & 7) << 2);
                sb[(tile * 32 + lp) * 2 + sl] = tf32r(vals[t]);
            }
        }
    };

    fetchH(0);
    scatH(sAb, sBb);
    __syncthreads();

#pragma unroll 1
    for (int ch = 0; ch < 8; ch++) {
        const int s = ch & 1;
        if (ch + 1 < 8) fetchH((ch + 1) << 5);
        const uint32_t* sa = sAb + s * 4096;
        const uint32_t* sb = sBb + s * 2048;
#pragma unroll
        for (int kk = 0; kk < 4; kk++) {
            uint32_t af[4][4];
            uint32_t bf[2][2];
#pragma unroll
            for (int im = 0; im < 4; im++) {
                int tile = kk * 8 + wm * 4 + im;
                int lp = lane ^ ((tile >> 3) << 2);
                uint4 u = *(const uint4*)(sa + (tile * 32 + lp) * 4);
                af[im][0] = u.x; af[im][1] = u.y; af[im][2] = u.z; af[im][3] = u.w;
            }
#pragma unroll
            for (int in = 0; in < 2; in++) {
                int tile = kk * 8 + wn * 2 + in;
                int lp = lane ^ ((tile & 7) << 2);
                uint2 u = *(const uint2*)(sb + (tile * 32 + lp) * 2);
                bf[in][0] = u.x; bf[in][1] = u.y;
            }
#pragma unroll
            for (int im = 0; im < 4; im++)
#pragma unroll
                for (int in = 0; in < 2; in++)
                    asm volatile(
                        "mma.sync.aligned.m16n8k8.row.col.f32.tf32.tf32.f32 "
                        "{%0,%1,%2,%3}, {%4,%5,%6,%7}, {%8,%9}, {%0,%1,%2,%3};"
                        : "+f"(acc[im][in][0]), "+f"(acc[im][in][1]),
                          "+f"(acc[im][in][2]), "+f"(acc[im][in][3])
                        : "r"(af[im][0]), "r"(af[im][1]), "r"(af[im][2]), "r"(af[im][3]),
                          "r"(bf[in][0]), "r"(bf[in][1]));
        }
        if (ch + 1 < 8) scatH(sAb + (s ^ 1) * 4096, sBb + (s ^ 1) * 2048);
        __syncthreads();
    }

#pragma unroll
    for (int im = 0; im < 4; im++) {
        int rl = row0 + wm * 64 + im * 16 + (lane >> 2);
        int rh = rl + 8;
#pragma unroll
        for (int in = 0; in < 2; in++) {
            int cc = wn * 16 + in * 8 + (lane & 3) * 2;
            if (cc >= CLS) continue;
            float b0 = bias[cc], b1 = bias[cc + 1];
            if (rl < M) {
                float2 v = make_float2(acc[im][in][0] + b0, acc[im][in][1] + b1);
                *(float2*)(C + (size_t)rl * CLS + cc) = v;
            }
            if (rh < M) {
                float2 v = make_float2(acc[im][in][2] + b0, acc[im][in][3] + b1);
                *(float2*)(C + (size_t)rh * CLS + cc) = v;
            }
        }
    }
}

// ---------------- init (degrees + counts + both stat sets) ----------------
__global__ void init_k(int Nn) {
    int i = blockIdx.x * blockDim.x + threadIdx.x;
    if (i < Nn) {
        g_degout[i] = 0.0f;
        g_degin[i] = 0.0f;
        g_cnt[i] = 0;
    }
    if (i < 2 * D) {
        g_sum[i] = 0.0f;
        g_sumsq[i] = 0.0f;
    }
}

__global__ void deg_k(const int* __restrict__ src, const int* __restrict__ dst, int E) {
    int e = blockIdx.x * blockDim.x + threadIdx.x;
    if (e < E) {
        atomicAdd(&g_degout[src[e]], 1.0f);
        atomicAdd(&g_degin[dst[e]], 1.0f);
        atomicAdd(&g_cnt[dst[e]], 1);
    }
}

__global__ void norm_k(int n) {
    int i = blockIdx.x * blockDim.x + threadIdx.x;
    if (i < n) {
        g_ns[i] = rsqrtf(fmaxf(g_degout[i], 1.0f));
        g_nd[i] = rsqrtf(fmaxf(g_degin[i], 1.0f));
    }
}

__global__ void scan1_k(int Nn) {
    __shared__ int sh[256];
    int i = blockIdx.x * 256 + threadIdx.x;
    int v = (i < Nn) ? g_cnt[i] : 0;
    sh[threadIdx.x] = v;
    __syncthreads();
    for (int off = 1; off < 256; off <<= 1) {
        int t = (threadIdx.x >= off) ? sh[threadIdx.x - off] : 0;
        __syncthreads();
        sh[threadIdx.x] += t;
        __syncthreads();
    }
    if (i < Nn) g_rowptr[i] = sh[threadIdx.x] - v;
    if (threadIdx.x == 255) g_bsum[blockIdx.x] = sh[255];
}

__global__ void scan2_k(int nb) {
    __shared__ int sh[256];
    int v = (threadIdx.x < nb) ? g_bsum[threadIdx.x] : 0;
    sh[threadIdx.x] = v;
    __syncthreads();
    for (int off = 1; off < 256; off <<= 1) {
        int t = (threadIdx.x >= off) ? sh[threadIdx.x - off] : 0;
        __syncthreads();
        sh[threadIdx.x] += t;
        __syncthreads();
    }
    g_boff[threadIdx.x] = sh[threadIdx.x] - v;
}

__global__ void scan3_k(int Nn, int E) {
    int i = blockIdx.x * 256 + threadIdx.x;
    if (i < Nn) {
        int r = g_rowptr[i] + g_boff[blockIdx.x];
        g_rowptr[i] = r;
        g_cursor[i] = r;
    }
    if (i == 0) g_rowptr[Nn] = E;
}

__global__ void fill_k(const int* __restrict__ src, const int* __restrict__ dst, int E) {
    int e = blockIdx.x * blockDim.x + threadIdx.x;
    if (e < E) {
        int pos = atomicAdd(&g_cursor[dst[e]], 1);
        g_esrc[pos] = src[e];
    }
}

// ---------------- CSR gather SpMM (fp16 in/out, fp32 accum) — R11 version ---------
__global__ __launch_bounds__(256) void spmmh_k(const __half* __restrict__ X,
                                               __half* __restrict__ Mo, int Nn) {
    int node = blockIdx.x * 4 + (threadIdx.x >> 6);
    if (node >= Nn) return;
    int c0 = (threadIdx.x & 63) * 4;
    int beg = g_rowptr[node], end = g_rowptr[node + 1];
    float a0 = 0.f, a1 = 0.f, a2 = 0.f, a3 = 0.f;
    for (int j = beg; j < end; j++) {
        int s = g_esrc[j];
        float sc = g_ns[s];
        uint2 u = *(const uint2*)(X + (size_t)s * D + c0);
        float2 f0 = __half22float2(*(__half2*)&u.x);
        float2 f1 = __half22float2(*(__half2*)&u.y);
        a0 += f0.x * sc; a1 += f0.y * sc; a2 += f1.x * sc; a3 += f1.y * sc;
    }
    float nd = g_nd[node];
    __half2 o0 = __floats2half2_rn(a0 * nd, a1 * nd);
    __half2 o1 = __floats2half2_rn(a2 * nd, a3 * nd);
    uint2 o;
    o.x = *(uint32_t*)&o0;
    o.y = *(uint32_t*)&o1;
    *(uint2*)(Mo + (size_t)node * D + c0) = o;
}

// ---------------- batchnorm finalize + apply (fp16) ----------------
__global__ void bnfin_k(const float* __restrict__ gamma, const float* __restrict__ beta,
                        const float* __restrict__ psum, const float* __restrict__ psumsq,
                        float invN) {
    int c = threadIdx.x;
    float mean = psum[c] * invN;
    float var = psumsq[c] * invN - mean * mean;
    float sc = gamma[c] * rsqrtf(var + 1e-5f);
    g_scale[c] = sc;
    g_shift[c] = beta[c] - mean * sc;
}

__device__ __forceinline__ float elu1(float v) { return v > 0.0f ? v : expm1f(v); }

__global__ void bnapplyh_k(uint4* __restrict__ X, int n8) {
    int i = blockIdx.x * blockDim.x + threadIdx.x;
    if (i >= n8) return;
    int c = (i & 31) * 8;
    uint4 u = X[i];
    __half2* h = (__half2*)&u;
#pragma unroll
    for (int t = 0; t < 4; t++) {
        float2 f = __half22float2(h[t]);
        f.x = elu1(f.x * g_scale[c + 2 * t] + g_shift[c + 2 * t]);
        f.y = elu1(f.y * g_scale[c + 2 * t + 1] + g_shift[c + 2 * t + 1]);
        h[t] = __floats2half2_rn(f.x, f.y);
    }
    X[i] = u;
}

// ---------------- host orchestration ----------------
static inline int cdiv(int a, int b) { return (a + b - 1) / b; }

extern "C" void kernel_launch(void* const* d_in, const int* in_sizes, int n_in,
                              void* d_out, int out_size) {
    const float* feat  = (const float*)d_in[0];
    const int*   src   = (const int*)d_in[1];
    const int*   dst   = (const int*)d_in[2];
    const float* W_fc  = (const float*)d_in[3];
    const float* b_fc  = (const float*)d_in[4];
    const float* W1    = (const float*)d_in[5];
    const float* b1    = (const float*)d_in[6];
    const float* W2    = (const float*)d_in[7];
    const float* b2    = (const float*)d_in[8];
    const float* W3    = (const float*)d_in[9];
    const float* b3    = (const float*)d_in[10];
    const float* gamma = (const float*)d_in[11];
    const float* beta  = (const float*)d_in[12];
    const float* W_lin = (const float*)d_in[13];
    const float* b_lin = (const float*)d_in[14];
    float* out = (float*)d_out;

    int N = in_sizes[0] / F;  // 50000
    int E = in_sizes[1];      // 300000

    cudaFuncSetAttribute(h_gemm_ca, cudaFuncAttributeMaxDynamicSharedMemorySize, GEMM_SMEM_CA);
    cudaFuncSetAttribute(h_gemm_rb<1>, cudaFuncAttributeMaxDynamicSharedMemorySize, GEMM_SMEM_RB);
    cudaFuncSetAttribute(h_gemm_rb<0>, cudaFuncAttributeMaxDynamicSharedMemorySize, GEMM_SMEM_RB);
    cudaFuncSetAttribute(head_mma_k, cudaFuncAttributeMaxDynamicSharedMemorySize, HEAD_SMEM);

    __half *pFh, *pXh, *pYh, *pMh, *pWth;
    float *pSum, *pSumsq;
    cudaGetSymbolAddress((void**)&pFh, g_Fh);
    cudaGetSymbolAddress((void**)&pXh, g_Xh);
    cudaGetSymbolAddress((void**)&pYh, g_Yh);
    cudaGetSymbolAddress((void**)&pMh, g_Mh);
    cudaGetSymbolAddress((void**)&pWth, g_Wth);
    cudaGetSymbolAddress((void**)&pSum, g_sum);
    cudaGetSymbolAddress((void**)&pSumsq, g_sumsq);

    const int ND = N * D;
    const int TB = 256;
    const int nb = cdiv(N, 256);
    const dim3 ggrid(2, cdiv(N, 128));
    const dim3 hgrid(1, cdiv(N, 128));
    const dim3 tthr(32, 8);
    const int sgrid = cdiv(N, 4);

    // ---- FC path first so the FC GEMM is launch #4 for ncu ----
    f2h_k<<<cdiv(N * F / 4, TB), TB>>>((const float4*)feat, (uint2*)pFh, N * F / 4);  // 1
    wt_k<<<dim3(F / 32, 8), tthr>>>(W_fc, pWth, F);                                   // 2
    init_k<<<cdiv(N, TB), TB>>>(N);                                                   // 3
    h_gemm_ca<<<ggrid, 256, GEMM_SMEM_CA>>>(pFh, pWth, b_fc, pXh, N, F);              // 4 (profiled)

    // ---- degree norms + CSR build (FC's Wt no longer needed after launch 4) ----
    deg_k<<<cdiv(E, TB), TB>>>(src, dst, E);
    norm_k<<<cdiv(N, TB), TB>>>(N);
    scan1_k<<<nb, 256>>>(N);
    scan2_k<<<1, 256>>>(nb);
    scan3_k<<<nb, 256>>>(N, E);
    fill_k<<<cdiv(E, TB), TB>>>(src, dst, E);
    wt3_k<<<dim3(8, 8, 3), tthr>>>(W1, W2, W3);  // all three layer weights at once

    // ---- layer 1 ----
    spmmh_k<<<sgrid, 256>>>(pXh, pMh, N);
    h_gemm_rb<1><<<ggrid, 256, GEMM_SMEM_RB>>>(pMh, pWth, b1, pYh, N, D, pSum, pSumsq);
    bnfin_k<<<1, D>>>(gamma, beta, pSum, pSumsq, 1.0f / (float)N);
    bnapplyh_k<<<cdiv(ND / 8, TB), TB>>>((uint4*)pYh, ND / 8);

    // ---- layer 2 ----
    spmmh_k<<<sgrid, 256>>>(pYh, pMh, N);
    h_gemm_rb<1><<<ggrid, 256, GEMM_SMEM_RB>>>(pMh, pWth + 65536, b2, pXh, N, D,
                                               pSum + D, pSumsq + D);
    bnfin_k<<<1, D>>>(gamma, beta, pSum + D, pSumsq + D, 1.0f / (float)N);
    bnapplyh_k<<<cdiv(ND / 8, TB), TB>>>((uint4*)pXh, ND / 8);

    // ---- layer 3: gconv -> out[0 : N*D] fp32 ----
    spmmh_k<<<sgrid, 256>>>(pXh, pMh, N);
    h_gemm_rb<0><<<ggrid, 256, GEMM_SMEM_RB>>>(pMh, pWth + 2 * 65536, b3, out, N, D,
                                               nullptr, nullptr);

    // ---- head: logits = x @ W_lin + b_lin ----
    head_mma_k<<<hgrid, 256, HEAD_SMEM>>>(out, W_lin, b_lin, out + (size_t)N * D, N);
}

// round 17
// speedup vs baseline: 1.0307x; 1.0056x over previous
#include <cuda_runtime.h>
#include <cuda_fp16.h>
#include <cstdint>
#include <math.h>

#define D 256
#define F 1024
#define CLS 40
#define NMAX 50000
#define EMAX 300000
#define ROWW 20  // padded words per 32-half tile row (bank-conflict-free bijection)

// ---------------- scratch (static device memory; no allocations) ----------------
__device__ __half g_Fh[NMAX * F];     // fp16 copy of feat
__device__ __half g_Xh[NMAX * D];
__device__ __half g_Yh[NMAX * D];
__device__ __half g_Mh[NMAX * D];
__device__ __half g_Wth[256 * 1024];  // fp16 Wt: FC uses all; layers use +l*65536
__device__ float g_degout[NMAX];
__device__ float g_degin[NMAX];
__device__ float g_ns[NMAX];
__device__ float g_nd[NMAX];
__device__ float g_sum[2 * D];        // two stat sets (layer1, layer2)
__device__ float g_sumsq[2 * D];
__device__ float g_scale[D];
__device__ float g_shift[D];
// CSR by dst
__device__ int g_cnt[NMAX];
__device__ int g_rowptr[NMAX + 1];
__device__ int g_cursor[NMAX];
__device__ int g_esrc[EMAX];
__device__ int g_bsum[256];
__device__ int g_boff[256];

__device__ __forceinline__ uint32_t tf32r(float x) {
    uint32_t r;
    asm("cvt.rna.tf32.f32 %0, %1;" : "=r"(r) : "f"(x));
    return r;
}
__device__ __forceinline__ uint32_t h2pack(float lo, float hi) {
    __half2 h = __floats2half2_rn(lo, hi);
    return *(uint32_t*)&h;
}

// ---------------- feat fp32 -> fp16 ----------------
__global__ void f2h_k(const float4* __restrict__ in, uint2* __restrict__ out, int n4) {
    int i = blockIdx.x * blockDim.x + threadIdx.x;
    if (i >= n4) return;
    float4 v = in[i];
    uint2 o;
    o.x = h2pack(v.x, v.y);
    o.y = h2pack(v.z, v.w);
    out[i] = o;
}

// ---------------- weight transpose+convert: W[K][256] fp32 -> Wt[256][K] fp16 ----
__global__ void wt_k(const float* __restrict__ W, __half* __restrict__ Wt, int K) {
    __shared__ float t[32][33];
    int k0 = blockIdx.x * 32, n0 = blockIdx.y * 32;
    int x = threadIdx.x, y = threadIdx.y;  // 32 x 8
    for (int j = y; j < 32; j += 8) t[j][x] = W[(size_t)(k0 + j) * 256 + n0 + x];
    __syncthreads();
    for (int j = y; j < 32; j += 8)
        Wt[(size_t)(n0 + j) * K + k0 + x] = __float2half(t[x][j]);
}

// batched: 3 D-layer weights (K=256) -> g_Wth + z*65536
__global__ void wt3_k(const float* __restrict__ W1, const float* __restrict__ W2,
                      const float* __restrict__ W3) {
    __shared__ float t[32][33];
    const float* W = (blockIdx.z == 0) ? W1 : (blockIdx.z == 1) ? W2 : W3;
    __half* Wt = g_Wth + (size_t)blockIdx.z * 65536;
    int k0 = blockIdx.x * 32, n0 = blockIdx.y * 32;
    int x = threadIdx.x, y = threadIdx.y;
    for (int j = y; j < 32; j += 8) t[j][x] = W[(size_t)(k0 + j) * 256 + n0 + x];
    __syncthreads();
    for (int j = y; j < 32; j += 8)
        Wt[(size_t)(n0 + j) * 256 + k0 + x] = __float2half(t[x][j]);
}

// ================= shared GEMM building blocks =================
#define TILE_WORDS (128 * ROWW)  // 2560 words per A or B buffer

// ldmatrix-based chunk compute (used by the long-K FC kernel).
__device__ __forceinline__ void gemm_compute_chunk_ldm(
    uint32_t sA, uint32_t sB, int wm, int wn, int lane, float (&acc)[4][4][4]) {
    const int lr = lane & 15;
    const int lc = lane >> 4;
#pragma unroll
    for (int kk = 0; kk < 2; kk++) {
        uint32_t afr[4][4];
        uint32_t bfr[4][2];
        const uint32_t coff = (kk * 16 + lc * 8) * 2;
#pragma unroll
        for (int im = 0; im < 4; im++) {
            int m = wm * 64 + im * 16 + lr;
            uint32_t addr = sA + m * (ROWW * 4) + coff;
            asm volatile(
                "ldmatrix.sync.aligned.m8n8.x4.shared.b16 {%0,%1,%2,%3}, [%4];"
                : "=r"(afr[im][0]), "=r"(afr[im][1]),
                  "=r"(afr[im][2]), "=r"(afr[im][3])
                : "r"(addr));
        }
#pragma unroll
        for (int ib = 0; ib < 2; ib++) {
            int n = wn * 32 + ib * 16 + lr;
            uint32_t addr = sB + n * (ROWW * 4) + coff;
            uint32_t r0, r1, r2, r3;
            asm volatile(
                "ldmatrix.sync.aligned.m8n8.x4.shared.b16 {%0,%1,%2,%3}, [%4];"
                : "=r"(r0), "=r"(r1), "=r"(r2), "=r"(r3)
                : "r"(addr));
            bfr[2 * ib][0] = r0; bfr[2 * ib + 1][0] = r1;
            bfr[2 * ib][1] = r2; bfr[2 * ib + 1][1] = r3;
        }
#pragma unroll
        for (int im = 0; im < 4; im++)
#pragma unroll
            for (int in = 0; in < 4; in++)
                asm volatile(
                    "mma.sync.aligned.m16n8k16.row.col.f32.f16.f16.f32 "
                    "{%0,%1,%2,%3}, {%4,%5,%6,%7}, {%8,%9}, {%0,%1,%2,%3};"
                    : "+f"(acc[im][in][0]), "+f"(acc[im][in][1]),
                      "+f"(acc[im][in][2]), "+f"(acc[im][in][3])
                    : "r"(afr[im][0]), "r"(afr[im][1]), "r"(afr[im][2]), "r"(afr[im][3]),
                      "r"(bfr[in][0]), "r"(bfr[in][1]));
    }
}

// Shared epilogue: bias, store (fp16 or fp32), optional fused column stats.
template <int C_HALF>
__device__ __forceinline__ void gemm_epilogue(
    void* Cv, const float* bias, int M, int row0, int col0,
    int wm, int wn, int lane, float (&acc)[4][4][4],
    float* psum, float* psumsq) {
    float s_[4][2] = {{0.f}}, q_[4][2] = {{0.f}};
#pragma unroll
    for (int im = 0; im < 4; im++) {
        int rl = row0 + wm * 64 + im * 16 + (lane >> 2);
        int rh = rl + 8;
        bool vl = rl < M, vh = rh < M;
#pragma unroll
        for (int in = 0; in < 4; in++) {
            int cc = col0 + wn * 32 + in * 8 + (lane & 3) * 2;
            float b0 = bias[cc], b1 = bias[cc + 1];
            float v0 = acc[im][in][0] + b0, v1 = acc[im][in][1] + b1;
            float v2 = acc[im][in][2] + b0, v3 = acc[im][in][3] + b1;
            if (vl) {
                if (C_HALF)
                    *(__half2*)((__half*)Cv + (size_t)rl * 256 + cc) = __floats2half2_rn(v0, v1);
                else
                    *(float2*)((float*)Cv + (size_t)rl * 256 + cc) = make_float2(v0, v1);
                s_[in][0] += v0; q_[in][0] += v0 * v0;
                s_[in][1] += v1; q_[in][1] += v1 * v1;
            }
            if (vh) {
                if (C_HALF)
                    *(__half2*)((__half*)Cv + (size_t)rh * 256 + cc) = __floats2half2_rn(v2, v3);
                else
                    *(float2*)((float*)Cv + (size_t)rh * 256 + cc) = make_float2(v2, v3);
                s_[in][0] += v2; q_[in][0] += v2 * v2;
                s_[in][1] += v3; q_[in][1] += v3 * v3;
            }
        }
    }
    if (psum != nullptr) {
#pragma unroll
        for (int in = 0; in < 4; in++)
#pragma unroll
            for (int t = 0; t < 2; t++) {
#pragma unroll
                for (int m = 4; m < 32; m <<= 1) {
                    s_[in][t] += __shfl_xor_sync(0xFFFFFFFF, s_[in][t], m);
                    q_[in][t] += __shfl_xor_sync(0xFFFFFFFF, q_[in][t], m);
                }
            }
        if ((lane >> 2) == 0) {
#pragma unroll
            for (int in = 0; in < 4; in++)
#pragma unroll
                for (int t = 0; t < 2; t++) {
                    int cc = col0 + wn * 32 + in * 8 + (lane & 3) * 2 + t;
                    atomicAdd(&psum[cc], s_[in][t]);
                    atomicAdd(&psumsq[cc], q_[in][t]);
                }
        }
    }
}

// ---------------- FC GEMM: cp.async 2-stage + ldmatrix (2 CTAs/SM) ----------------
#define GEMM_SMEM_CA (2 * 2 * TILE_WORDS * 4)  // 40960 B

__global__ __launch_bounds__(256, 2) void h_gemm_ca(
    const __half* __restrict__ Ah, const __half* __restrict__ Wt,
    const float* __restrict__ bias, void* __restrict__ Cv,
    int M, int K) {
    extern __shared__ uint32_t dsm[];
    const uint32_t sbase = (uint32_t)__cvta_generic_to_shared(dsm);

    const int tid = threadIdx.x;
    const int lane = tid & 31;
    const int wid = tid >> 5;
    const int wm = wid >> 2, wn = wid & 3;
    const int row0 = blockIdx.y * 128;
    const int col0 = blockIdx.x * 128;

    float acc[4][4][4];
#pragma unroll
    for (int i = 0; i < 4; i++)
#pragma unroll
        for (int j = 0; j < 4; j++)
#pragma unroll
            for (int t = 0; t < 4; t++) acc[i][j][t] = 0.0f;

    const int nch = K >> 5;

    auto issue = [&](int buf, int k0) {
        uint32_t sA = sbase + buf * 2 * TILE_WORDS * 4;
        uint32_t sB = sA + TILE_WORDS * 4;
#pragma unroll
        for (int j = 0; j < 2; j++) {
            int id = tid + 256 * j;
            int r = id >> 2, sq = id & 3;
            uint32_t soff = (r * ROWW + 4 * sq) * 4;
            int gr = row0 + r;
            int grc = gr < M ? gr : 0;
            const __half* ga = Ah + (size_t)grc * K + k0 + 8 * sq;
            int sz = (gr < M) ? 16 : 0;
            asm volatile("cp.async.cg.shared.global [%0], [%1], 16, %2;"
                         :: "r"(sA + soff), "l"(ga), "r"(sz) : "memory");
            const __half* gb = Wt + (size_t)(col0 + r) * K + k0 + 8 * sq;
            asm volatile("cp.async.cg.shared.global [%0], [%1], 16;"
                         :: "r"(sB + soff), "l"(gb) : "memory");
        }
        asm volatile("cp.async.commit_group;" ::: "memory");
    };

    issue(0, 0);

    for (int ch = 0; ch < nch; ch++) {
        const int s = ch & 1;
        // wait for chunk ch's group (only pending one), then barrier.
        asm volatile("cp.async.wait_group 0;" ::: "memory");
        __syncthreads();
        // safe to overwrite buf s^1: all warps finished compute(ch-1) before this barrier.
        if (ch + 1 < nch) issue(s ^ 1, (ch + 1) << 5);
        uint32_t sA = sbase + s * 2 * TILE_WORDS * 4;
        gemm_compute_chunk_ldm(sA, sA + TILE_WORDS * 4, wm, wn, lane, acc);
    }

    gemm_epilogue<1>(Cv, bias, M, row0, col0, wm, wn, lane, acc, nullptr, nullptr);
}

// ---------------- D-GEMM: register double-buffer + scalar fragment LDS ----------
#define GEMM_SMEM_RB (4 * TILE_WORDS * 4)  // 40960 B

template <int C_HALF>
__global__ __launch_bounds__(256, 2) void h_gemm_rb(
    const __half* __restrict__ Ah, const __half* __restrict__ Wt,
    const float* __restrict__ bias, void* __restrict__ Cv,
    int M, int K, float* psum, float* psumsq) {
    extern __shared__ uint32_t dsm[];

    const int tid = threadIdx.x;
    const int lane = tid & 31;
    const int wid = tid >> 5;
    const int wm = wid >> 2, wn = wid & 3;
    const int row0 = blockIdx.y * 128;
    const int col0 = blockIdx.x * 128;

    const int srow = tid >> 2;  // 0..63
    const int sq = tid & 3;

    float acc[4][4][4];
#pragma unroll
    for (int i = 0; i < 4; i++)
#pragma unroll
        for (int j = 0; j < 4; j++)
#pragma unroll
            for (int t = 0; t < 4; t++) acc[i][j][t] = 0.0f;

    const int nch = K >> 5;
    uint4 ar[2], br[2];

    auto fetch = [&](int k0) {
#pragma unroll
        for (int jj = 0; jj < 2; jj++) {
            int r = srow + 64 * jj;
            int gr = row0 + r;
            ar[jj] = (gr < M) ? *(const uint4*)(Ah + (size_t)gr * K + k0 + 8 * sq)
                              : make_uint4(0, 0, 0, 0);
            br[jj] = *(const uint4*)(Wt + (size_t)(col0 + r) * K + k0 + 8 * sq);
        }
    };
    auto scat = [&](uint32_t* sA, uint32_t* sB) {
#pragma unroll
        for (int jj = 0; jj < 2; jj++) {
            int r = srow + 64 * jj;
            *(uint4*)(sA + r * ROWW + 4 * sq) = ar[jj];
            *(uint4*)(sB + r * ROWW + 4 * sq) = br[jj];
        }
    };

    fetch(0);
    scat(dsm, dsm + TILE_WORDS);
    __syncthreads();

    const int lq = lane & 3;
    const int lr = lane >> 2;

    for (int ch = 0; ch < nch; ch++) {
        const int s = ch & 1;
        if (ch + 1 < nch) fetch((ch + 1) << 5);

        const uint32_t* sA = dsm + s * 2 * TILE_WORDS;
        const uint32_t* sB = sA + TILE_WORDS;
#pragma unroll
        for (int kk = 0; kk < 2; kk++) {
            uint32_t afr[4][4];
            uint32_t bfr[4][2];
#pragma unroll
            for (int im = 0; im < 4; im++) {
                int m = wm * 64 + im * 16 + lr;
                const uint32_t* p0 = sA + m * ROWW + kk * 8 + lq;
                const uint32_t* p1 = sA + (m + 8) * ROWW + kk * 8 + lq;
                afr[im][0] = p0[0];
                afr[im][1] = p1[0];
                afr[im][2] = p0[4];
                afr[im][3] = p1[4];
            }
#pragma unroll
            for (int in = 0; in < 4; in++) {
                int n = wn * 32 + in * 8 + lr;
                const uint32_t* p = sB + n * ROWW + kk * 8 + lq;
                bfr[in][0] = p[0];
                bfr[in][1] = p[4];
            }
#pragma unroll
            for (int im = 0; im < 4; im++)
#pragma unroll
                for (int in = 0; in < 4; in++)
                    asm volatile(
                        "mma.sync.aligned.m16n8k16.row.col.f32.f16.f16.f32 "
                        "{%0,%1,%2,%3}, {%4,%5,%6,%7}, {%8,%9}, {%0,%1,%2,%3};"
                        : "+f"(acc[im][in][0]), "+f"(acc[im][in][1]),
                          "+f"(acc[im][in][2]), "+f"(acc[im][in][3])
                        : "r"(afr[im][0]), "r"(afr[im][1]), "r"(afr[im][2]), "r"(afr[im][3]),
                          "r"(bfr[in][0]), "r"(bfr[in][1]));
        }
        if (ch + 1 < nch) {
            uint32_t* nA = dsm + (s ^ 1) * 2 * TILE_WORDS;
            scat(nA, nA + TILE_WORDS);
        }
        __syncthreads();
    }

    gemm_epilogue<C_HALF>(Cv, bias, M, row0, col0, wm, wn, lane, acc, psum, psumsq);
}

// ---------------- tf32 mma head (K=256, Nc=40, padded to 64) ----------------
#define HEAD_SMEM 49152
__global__ __launch_bounds__(256, 2) void head_mma_k(
    const float* __restrict__ A, const float* __restrict__ W,
    const float* __restrict__ bias, float* __restrict__ C, int M) {
    extern __shared__ uint32_t hsm[];
    uint32_t* sAb = hsm;
    uint32_t* sBb = hsm + 8192;

    const int tid = threadIdx.x;
    const int lane = tid & 31;
    const int wid = tid >> 5;
    const int wm = wid >> 2, wn = wid & 3;
    const int row0 = blockIdx.y * 128;

    const int c4 = (tid & 7) * 4;
    const int rbase = tid >> 3;
    const int bn4 = (tid & 15) * 4;
    const int bkbase = tid >> 4;

    float acc[4][2][4];
#pragma unroll
    for (int i = 0; i < 4; i++)
#pragma unroll
        for (int j = 0; j < 2; j++)
#pragma unroll
            for (int t = 0; t < 4; t++) acc[i][j][t] = 0.0f;

    float4 av[4], bv[2];

    auto fetchH = [&](int k0) {
#pragma unroll
        for (int j = 0; j < 4; j++) {
            int gr = row0 + rbase + 32 * j;
            av[j] = (gr < M) ? *(const float4*)(A + (size_t)gr * 256 + k0 + c4)
                             : make_float4(0.f, 0.f, 0.f, 0.f);
        }
#pragma unroll
        for (int j = 0; j < 2; j++) {
            int k = bkbase + 16 * j;
            bv[j] = (bn4 < CLS) ? *(const float4*)(W + (size_t)(k0 + k) * CLS + bn4)
                                : make_float4(0.f, 0.f, 0.f, 0.f);
        }
    };
    auto scatH = [&](uint32_t* sa, uint32_t* sb) {
#pragma unroll
        for (int j = 0; j < 4; j++) {
            int r = rbase + 32 * j;
            int r16 = r & 15, mt = r >> 4;
            float vals[4] = {av[j].x, av[j].y, av[j].z, av[j].w};
#pragma unroll
            for (int t = 0; t < 4; t++) {
                int c = c4 + t;
                int kk = c >> 3, c8 = c & 7;
                int ln = (r16 & 7) * 4 + (c8 & 3);
                int sl = (r16 >> 3) | ((c8 >> 2) << 1);
                int tile = kk * 8 + mt;
                int lp = ln ^ ((tile >> 3) << 2);
                sa[(tile * 32 + lp) * 4 + sl] = tf32r(vals[t]);
            }
        }
#pragma unroll
        for (int j = 0; j < 2; j++) {
            int k = bkbase + 16 * j;
            int kk = k >> 3, k8 = k & 7;
            int sl = k8 >> 2, l4 = k8 & 3;
            float vals[4] = {bv[j].x, bv[j].y, bv[j].z, bv[j].w};
#pragma unroll
            for (int t = 0; t < 4; t++) {
                int n = bn4 + t;
                int nt = n >> 3, n8 = n & 7;
                int tile = kk * 8 + nt;
                int ln = n8 * 4 + l4;
                int lp = ln ^ ((tile & 7) << 2);
                sb[(tile * 32 + lp) * 2 + sl] = tf32r(vals[t]);
            }
        }
    };

    fetchH(0);
    scatH(sAb, sBb);
    __syncthreads();

#pragma unroll 1
    for (int ch = 0; ch < 8; ch++) {
        const int s = ch & 1;
        if (ch + 1 < 8) fetchH((ch + 1) << 5);
        const uint32_t* sa = sAb + s * 4096;
        const uint32_t* sb = sBb + s * 2048;
#pragma unroll
        for (int kk = 0; kk < 4; kk++) {
            uint32_t af[4][4];
            uint32_t bf[2][2];
#pragma unroll
            for (int im = 0; im < 4; im++) {
                int tile = kk * 8 + wm * 4 + im;
                int lp = lane ^ ((tile >> 3) << 2);
                uint4 u = *(const uint4*)(sa + (tile * 32 + lp) * 4);
                af[im][0] = u.x; af[im][1] = u.y; af[im][2] = u.z; af[im][3] = u.w;
            }
#pragma unroll
            for (int in = 0; in < 2; in++) {
                int tile = kk * 8 + wn * 2 + in;
                int lp = lane ^ ((tile & 7) << 2);
                uint2 u = *(const uint2*)(sb + (tile * 32 + lp) * 2);
                bf[in][0] = u.x; bf[in][1] = u.y;
            }
#pragma unroll
            for (int im = 0; im < 4; im++)
#pragma unroll
                for (int in = 0; in < 2; in++)
                    asm volatile(
                        "mma.sync.aligned.m16n8k8.row.col.f32.tf32.tf32.f32 "
                        "{%0,%1,%2,%3}, {%4,%5,%6,%7}, {%8,%9}, {%0,%1,%2,%3};"
                        : "+f"(acc[im][in][0]), "+f"(acc[im][in][1]),
                          "+f"(acc[im][in][2]), "+f"(acc[im][in][3])
                        : "r"(af[im][0]), "r"(af[im][1]), "r"(af[im][2]), "r"(af[im][3]),
                          "r"(bf[in][0]), "r"(bf[in][1]));
        }
        if (ch + 1 < 8) scatH(sAb + (s ^ 1) * 4096, sBb + (s ^ 1) * 2048);
        __syncthreads();
    }

#pragma unroll
    for (int im = 0; im < 4; im++) {
        int rl = row0 + wm * 64 + im * 16 + (lane >> 2);
        int rh = rl + 8;
#pragma unroll
        for (int in = 0; in < 2; in++) {
            int cc = wn * 16 + in * 8 + (lane & 3) * 2;
            if (cc >= CLS) continue;
            float b0 = bias[cc], b1 = bias[cc + 1];
            if (rl < M) {
                float2 v = make_float2(acc[im][in][0] + b0, acc[im][in][1] + b1);
                *(float2*)(C + (size_t)rl * CLS + cc) = v;
            }
            if (rh < M) {
                float2 v = make_float2(acc[im][in][2] + b0, acc[im][in][3] + b1);
                *(float2*)(C + (size_t)rh * CLS + cc) = v;
            }
        }
    }
}

// ---------------- init (degrees + counts + both stat sets) ----------------
__global__ void init_k(int Nn) {
    int i = blockIdx.x * blockDim.x + threadIdx.x;
    if (i < Nn) {
        g_degout[i] = 0.0f;
        g_degin[i] = 0.0f;
        g_cnt[i] = 0;
    }
    if (i < 2 * D) {
        g_sum[i] = 0.0f;
        g_sumsq[i] = 0.0f;
    }
}

__global__ void deg_k(const int* __restrict__ src, const int* __restrict__ dst, int E) {
    int e = blockIdx.x * blockDim.x + threadIdx.x;
    if (e < E) {
        atomicAdd(&g_degout[src[e]], 1.0f);
        atomicAdd(&g_degin[dst[e]], 1.0f);
        atomicAdd(&g_cnt[dst[e]], 1);
    }
}

__global__ void norm_k(int n) {
    int i = blockIdx.x * blockDim.x + threadIdx.x;
    if (i < n) {
        g_ns[i] = rsqrtf(fmaxf(g_degout[i], 1.0f));
        g_nd[i] = rsqrtf(fmaxf(g_degin[i], 1.0f));
    }
}

__global__ void scan1_k(int Nn) {
    __shared__ int sh[256];
    int i = blockIdx.x * 256 + threadIdx.x;
    int v = (i < Nn) ? g_cnt[i] : 0;
    sh[threadIdx.x] = v;
    __syncthreads();
    for (int off = 1; off < 256; off <<= 1) {
        int t = (threadIdx.x >= off) ? sh[threadIdx.x - off] : 0;
        __syncthreads();
        sh[threadIdx.x] += t;
        __syncthreads();
    }
    if (i < Nn) g_rowptr[i] = sh[threadIdx.x] - v;
    if (threadIdx.x == 255) g_bsum[blockIdx.x] = sh[255];
}

__global__ void scan2_k(int nb) {
    __shared__ int sh[256];
    int v = (threadIdx.x < nb) ? g_bsum[threadIdx.x] : 0;
    sh[threadIdx.x] = v;
    __syncthreads();
    for (int off = 1; off < 256; off <<= 1) {
        int t = (threadIdx.x >= off) ? sh[threadIdx.x - off] : 0;
        __syncthreads();
        sh[threadIdx.x] += t;
        __syncthreads();
    }
    g_boff[threadIdx.x] = sh[threadIdx.x] - v;
}

__global__ void scan3_k(int Nn, int E) {
    int i = blockIdx.x * 256 + threadIdx.x;
    if (i < Nn) {
        int r = g_rowptr[i] + g_boff[blockIdx.x];
        g_rowptr[i] = r;
        g_cursor[i] = r;
    }
    if (i == 0) g_rowptr[Nn] = E;
}

__global__ void fill_k(const int* __restrict__ src, const int* __restrict__ dst, int E) {
    int e = blockIdx.x * blockDim.x + threadIdx.x;
    if (e < E) {
        int pos = atomicAdd(&g_cursor[dst[e]], 1);
        g_esrc[pos] = src[e];
    }
}

// ---------------- CSR gather SpMM (fp16 in/out, fp32 accum) ----------------
__global__ __launch_bounds__(256) void spmmh_k(const __half* __restrict__ X,
                                               __half* __restrict__ Mo, int Nn) {
    int node = blockIdx.x * 4 + (threadIdx.x >> 6);
    if (node >= Nn) return;
    int c0 = (threadIdx.x & 63) * 4;
    int beg = g_rowptr[node], end = g_rowptr[node + 1];
    float a0 = 0.f, a1 = 0.f, a2 = 0.f, a3 = 0.f;
    for (int j = beg; j < end; j++) {
        int s = g_esrc[j];
        float sc = g_ns[s];
        uint2 u = *(const uint2*)(X + (size_t)s * D + c0);
        float2 f0 = __half22float2(*(__half2*)&u.x);
        float2 f1 = __half22float2(*(__half2*)&u.y);
        a0 += f0.x * sc; a1 += f0.y * sc; a2 += f1.x * sc; a3 += f1.y * sc;
    }
    float nd = g_nd[node];
    __half2 o0 = __floats2half2_rn(a0 * nd, a1 * nd);
    __half2 o1 = __floats2half2_rn(a2 * nd, a3 * nd);
    uint2 o;
    o.x = *(uint32_t*)&o0;
    o.y = *(uint32_t*)&o1;
    *(uint2*)(Mo + (size_t)node * D + c0) = o;
}

// ---------------- batchnorm finalize + apply (fp16) ----------------
__global__ void bnfin_k(const float* __restrict__ gamma, const float* __restrict__ beta,
                        const float* __restrict__ psum, const float* __restrict__ psumsq,
                        float invN) {
    int c = threadIdx.x;
    float mean = psum[c] * invN;
    float var = psumsq[c] * invN - mean * mean;
    float sc = gamma[c] * rsqrtf(var + 1e-5f);
    g_scale[c] = sc;
    g_shift[c] = beta[c] - mean * sc;
}

// fast ELU: exp(v)-1 via hardware EX2 (|abs err| ~1e-7 near 0 — fine at 1e-3 tol)
__device__ __forceinline__ float elu1(float v) {
    return v > 0.0f ? v : (__expf(v) - 1.0f);
}

__global__ void bnapplyh_k(uint4* __restrict__ X, int n8) {
    int i = blockIdx.x * blockDim.x + threadIdx.x;
    if (i >= n8) return;
    int c = (i & 31) * 8;
    uint4 u = X[i];
    __half2* h = (__half2*)&u;
#pragma unroll
    for (int t = 0; t < 4; t++) {
        float2 f = __half22float2(h[t]);
        f.x = elu1(f.x * g_scale[c + 2 * t] + g_shift[c + 2 * t]);
        f.y = elu1(f.y * g_scale[c + 2 * t + 1] + g_shift[c + 2 * t + 1]);
        h[t] = __floats2half2_rn(f.x, f.y);
    }
    X[i] = u;
}

// ---------------- host orchestration ----------------
static inline int cdiv(int a, int b) { return (a + b - 1) / b; }

extern "C" void kernel_launch(void* const* d_in, const int* in_sizes, int n_in,
                              void* d_out, int out_size) {
    const float* feat  = (const float*)d_in[0];
    const int*   src   = (const int*)d_in[1];
    const int*   dst   = (const int*)d_in[2];
    const float* W_fc  = (const float*)d_in[3];
    const float* b_fc  = (const float*)d_in[4];
    const float* W1    = (const float*)d_in[5];
    const float* b1    = (const float*)d_in[6];
    const float* W2    = (const float*)d_in[7];
    const float* b2    = (const float*)d_in[8];
    const float* W3    = (const float*)d_in[9];
    const float* b3    = (const float*)d_in[10];
    const float* gamma = (const float*)d_in[11];
    const float* beta  = (const float*)d_in[12];
    const float* W_lin = (const float*)d_in[13];
    const float* b_lin = (const float*)d_in[14];
    float* out = (float*)d_out;

    int N = in_sizes[0] / F;  // 50000
    int E = in_sizes[1];      // 300000

    cudaFuncSetAttribute(h_gemm_ca, cudaFuncAttributeMaxDynamicSharedMemorySize, GEMM_SMEM_CA);
    cudaFuncSetAttribute(h_gemm_rb<1>, cudaFuncAttributeMaxDynamicSharedMemorySize, GEMM_SMEM_RB);
    cudaFuncSetAttribute(h_gemm_rb<0>, cudaFuncAttributeMaxDynamicSharedMemorySize, GEMM_SMEM_RB);
    cudaFuncSetAttribute(head_mma_k, cudaFuncAttributeMaxDynamicSharedMemorySize, HEAD_SMEM);

    __half *pFh, *pXh, *pYh, *pMh, *pWth;
    float *pSum, *pSumsq;
    cudaGetSymbolAddress((void**)&pFh, g_Fh);
    cudaGetSymbolAddress((void**)&pXh, g_Xh);
    cudaGetSymbolAddress((void**)&pYh, g_Yh);
    cudaGetSymbolAddress((void**)&pMh, g_Mh);
    cudaGetSymbolAddress((void**)&pWth, g_Wth);
    cudaGetSymbolAddress((void**)&pSum, g_sum);
    cudaGetSymbolAddress((void**)&pSumsq, g_sumsq);

    const int ND = N * D;
    const int TB = 256;
    const int nb = cdiv(N, 256);
    const dim3 ggrid(2, cdiv(N, 128));
    const dim3 hgrid(1, cdiv(N, 128));
    const dim3 tthr(32, 8);
    const int sgrid = cdiv(N, 4);

    // ---- FC path first so the FC GEMM is launch #4 for ncu ----
    f2h_k<<<cdiv(N * F / 4, TB), TB>>>((const float4*)feat, (uint2*)pFh, N * F / 4);  // 1
    wt_k<<<dim3(F / 32, 8), tthr>>>(W_fc, pWth, F);                                   // 2
    init_k<<<cdiv(N, TB), TB>>>(N);                                                   // 3
    h_gemm_ca<<<ggrid, 256, GEMM_SMEM_CA>>>(pFh, pWth, b_fc, pXh, N, F);              // 4 (profiled)

    // ---- degree norms + CSR build ----
    deg_k<<<cdiv(E, TB), TB>>>(src, dst, E);
    norm_k<<<cdiv(N, TB), TB>>>(N);
    scan1_k<<<nb, 256>>>(N);
    scan2_k<<<1, 256>>>(nb);
    scan3_k<<<nb, 256>>>(N, E);
    fill_k<<<cdiv(E, TB), TB>>>(src, dst, E);
    wt3_k<<<dim3(8, 8, 3), tthr>>>(W1, W2, W3);

    // ---- layer 1 ----
    spmmh_k<<<sgrid, 256>>>(pXh, pMh, N);
    h_gemm_rb<1><<<ggrid, 256, GEMM_SMEM_RB>>>(pMh, pWth, b1, pYh, N, D, pSum, pSumsq);
    bnfin_k<<<1, D>>>(gamma, beta, pSum, pSumsq, 1.0f / (float)N);
    bnapplyh_k<<<cdiv(ND / 8, TB), TB>>>((uint4*)pYh, ND / 8);

    // ---- layer 2 ----
    spmmh_k<<<sgrid, 256>>>(pYh, pMh, N);
    h_gemm_rb<1><<<ggrid, 256, GEMM_SMEM_RB>>>(pMh, pWth + 65536, b2, pXh, N, D,
                                               pSum + D, pSumsq + D);
    bnfin_k<<<1, D>>>(gamma, beta, pSum + D, pSumsq + D, 1.0f / (float)N);
    bnapplyh_k<<<cdiv(ND / 8, TB), TB>>>((uint4*)pXh, ND / 8);

    // ---- layer 3: gconv -> out[0 : N*D] fp32 ----
    spmmh_k<<<sgrid, 256>>>(pXh, pMh, N);
    h_gemm_rb<0><<<ggrid, 256, GEMM_SMEM_RB>>>(pMh, pWth + 2 * 65536, b3, out, N, D,
                                               nullptr, nullptr);

    // ---- head: logits = x @ W_lin + b_lin ----
    head_mma_k<<<hgrid, 256, HEAD_SMEM>>>(out, W_lin, b_lin, out + (size_t)N * D, N);
}